// round 1
// baseline (speedup 1.0000x reference)
#include <cuda_runtime.h>
#include <cstdint>

#define F  1024   // IN_PARTITIONS * IN_NODES
#define C  128    // OUT_CLASSES
#define B  2048   // BATCH
#define TB 16     // batch rows per block

// Packed softmax(weight) in (f,f+1)-pair layout: g_ew2[p*C + c] = pack(ew[c][2p], ew[c][2p+1])
__device__ unsigned long long g_ew2[(F / 2) * C];

// ---------- packed f32x2 helpers (Blackwell sm_103a) ----------
__device__ __forceinline__ void fma2(unsigned long long& d, unsigned long long a,
                                     unsigned long long b) {
    asm("fma.rn.f32x2 %0, %1, %2, %0;" : "+l"(d) : "l"(a), "l"(b));
}
__device__ __forceinline__ unsigned long long add2(unsigned long long a, unsigned long long b) {
    unsigned long long r;
    asm("add.rn.f32x2 %0, %1, %2;" : "=l"(r) : "l"(a), "l"(b));
    return r;
}
__device__ __forceinline__ unsigned long long packf2(float lo, float hi) {
    unsigned long long r;
    asm("mov.b64 %0, {%1, %2};" : "=l"(r) : "f"(lo), "f"(hi));
    return r;
}
__device__ __forceinline__ void unpack2(unsigned long long v, float& lo, float& hi) {
    asm("mov.b64 {%0, %1}, %2;" : "=f"(lo), "=f"(hi) : "l"(v));
}

// ---------- Kernel A: softmax of each weight row into packed-pair layout ----------
__global__ __launch_bounds__(256) void wprep_kernel(const float* __restrict__ w) {
    const int c = blockIdx.x;
    const int tid = threadIdx.x;
    __shared__ float red[8];

    float4 v = *reinterpret_cast<const float4*>(w + (size_t)c * F + tid * 4);

    // row max
    float m = fmaxf(fmaxf(v.x, v.y), fmaxf(v.z, v.w));
#pragma unroll
    for (int o = 16; o; o >>= 1) m = fmaxf(m, __shfl_xor_sync(0xffffffffu, m, o));
    if ((tid & 31) == 0) red[tid >> 5] = m;
    __syncthreads();
    m = red[0];
#pragma unroll
    for (int i = 1; i < 8; i++) m = fmaxf(m, red[i]);
    __syncthreads();

    // exp + row sum
    float e0 = __expf(v.x - m), e1 = __expf(v.y - m);
    float e2 = __expf(v.z - m), e3 = __expf(v.w - m);
    float s = (e0 + e1) + (e2 + e3);
#pragma unroll
    for (int o = 16; o; o >>= 1) s += __shfl_xor_sync(0xffffffffu, s, o);
    if ((tid & 31) == 0) red[tid >> 5] = s;
    __syncthreads();
    s = 0.0f;
#pragma unroll
    for (int i = 0; i < 8; i++) s += red[i];
    const float inv = 1.0f / s;

    // write packed pairs: thread covers f = 4*tid .. 4*tid+3 -> pairs 2*tid, 2*tid+1
    g_ew2[(size_t)(2 * tid) * C + c]     = packf2(e0 * inv, e1 * inv);
    g_ew2[(size_t)(2 * tid + 1) * C + c] = packf2(e2 * inv, e3 * inv);
}

// ---------- Kernel B: per 16-row tile: exp(x - rowmax) into smem, then GEMM + log ----------
__global__ __launch_bounds__(256) void lse_kernel(const float* __restrict__ x,
                                                  float* __restrict__ out) {
    extern __shared__ float smem[];
    float* ex = smem;                  // TB * F floats (64 KB), row-major
    float* mxs = smem + TB * F;        // TB floats
    unsigned long long* part =
        reinterpret_cast<unsigned long long*>(smem + TB * F + TB);  // C * TB ull (16 KB)

    const int tid = threadIdx.x;
    const int lane = tid & 31;
    const int warp = tid >> 5;  // 0..7
    const int b0 = blockIdx.x * TB;

    // ---- phase 1: per-row max (each warp reduces 2 rows) ----
#pragma unroll
    for (int rr = 0; rr < 2; rr++) {
        const int r = warp * 2 + rr;
        const float* xr = x + (size_t)(b0 + r) * F;
        float m = -3.4e38f;
        for (int f = lane; f < F; f += 32) m = fmaxf(m, xr[f]);
#pragma unroll
        for (int o = 16; o; o >>= 1) m = fmaxf(m, __shfl_xor_sync(0xffffffffu, m, o));
        if (lane == 0) mxs[r] = m;
    }
    __syncthreads();

    // ---- phase 2: ex[r][f] = exp(x - mx[r]) (coalesced read + write) ----
    const float* xb = x + (size_t)b0 * F;
    for (int idx = tid; idx < TB * F; idx += 256) {
        const int r = idx >> 10;  // F == 1024
        ex[idx] = __expf(xb[idx] - mxs[r]);
    }
    __syncthreads();

    // ---- phase 3: out[b0+r][c] = mx[r] + log( dot(ex[r], ew[c]) ) ----
    const int c = tid & (C - 1);
    const int half = tid >> 7;  // f-halves split across the two thread groups
    const unsigned long long* wp = g_ew2 + c;

    unsigned long long acc[TB];
#pragma unroll
    for (int r = 0; r < TB; r++) acc[r] = 0ull;

    const int pbeg = half * (F / 4);  // 256 pairs per half
#pragma unroll 1
    for (int p = pbeg; p < pbeg + (F / 4); p += 8) {
        // batch 8 weight-pair loads up front (MLP=8 against L2-hit latency)
        unsigned long long w[8];
#pragma unroll
        for (int j = 0; j < 8; j++) w[j] = wp[(size_t)(p + j) * C];

#pragma unroll
        for (int j = 0; j < 8; j += 2) {
            const int f = (p + j) << 1;  // multiple of 4 -> 16B-aligned smem reads
#pragma unroll
            for (int r = 0; r < TB; r++) {
                ulonglong2 e = *reinterpret_cast<const ulonglong2*>(ex + r * F + f);
                fma2(acc[r], e.x, w[j]);      // even/odd f packed in lanes
                fma2(acc[r], e.y, w[j + 1]);
            }
        }
    }

    // cross-half reduction (swizzled to avoid bank conflicts)
    if (half) {
#pragma unroll
        for (int r = 0; r < TB; r++) part[c * TB + ((r + c) & (TB - 1))] = acc[r];
    }
    __syncthreads();
    if (!half) {
#pragma unroll
        for (int r = 0; r < TB; r++) {
            const unsigned long long t = add2(acc[r], part[c * TB + ((r + c) & (TB - 1))]);
            float lo, hi;
            unpack2(t, lo, hi);
            out[(size_t)(b0 + r) * C + c] = mxs[r] + logf(lo + hi);
        }
    }
}

extern "C" void kernel_launch(void* const* d_in, const int* in_sizes, int n_in,
                              void* d_out, int out_size) {
    const float* x = (const float*)d_in[0];
    const float* w = (const float*)d_in[1];
    // robust to input-order surprises: weight has C*F elements, x has B*F
    if (n_in >= 2 && in_sizes[0] == C * F && in_sizes[1] == B * F) {
        const float* t = x; x = w; w = t;
    }
    float* out = (float*)d_out;

    const int smem_bytes = (TB * F + TB) * (int)sizeof(float) + C * TB * (int)sizeof(unsigned long long);
    cudaFuncSetAttribute(lse_kernel, cudaFuncAttributeMaxDynamicSharedMemorySize, smem_bytes);

    wprep_kernel<<<C, 256>>>(w);
    lse_kernel<<<B / TB, 256, smem_bytes>>>(x, out);
}

// round 4
// speedup vs baseline: 1.3032x; 1.3032x over previous
#include <cuda_runtime.h>
#include <cstdint>

#define F  1024   // IN_PARTITIONS * IN_NODES
#define C  128    // OUT_CLASSES
#define B  2048   // BATCH
#define TB 16     // batch rows per block
#define CH 64     // classes per block (class-split 2)

// softmax(weight) packed 4-consecutive-f per class: g_ew4[q*C + c] = {pack(f4q,f4q+1), pack(f4q+2,f4q+3)}
__device__ ulonglong2 g_ew4[(F / 4) * C];

// ---------- packed f32x2 helpers (Blackwell sm_103a) ----------
__device__ __forceinline__ void fma2(unsigned long long& d, unsigned long long a,
                                     unsigned long long b) {
    asm("fma.rn.f32x2 %0, %1, %2, %0;" : "+l"(d) : "l"(a), "l"(b));
}
__device__ __forceinline__ unsigned long long add2(unsigned long long a, unsigned long long b) {
    unsigned long long r;
    asm("add.rn.f32x2 %0, %1, %2;" : "=l"(r) : "l"(a), "l"(b));
    return r;
}
__device__ __forceinline__ unsigned long long packf2(float lo, float hi) {
    unsigned long long r;
    asm("mov.b64 %0, {%1, %2};" : "=l"(r) : "f"(lo), "f"(hi));
    return r;
}
__device__ __forceinline__ void unpack2(unsigned long long v, float& lo, float& hi) {
    asm("mov.b64 {%0, %1}, %2;" : "=f"(lo), "=f"(hi) : "l"(v));
}

// ---------- Kernel A: per-class softmax into packed-quad layout ----------
__global__ __launch_bounds__(256) void wprep_kernel(const float* __restrict__ w) {
    const int c = blockIdx.x;
    const int tid = threadIdx.x;
    __shared__ float red[8];

    float4 v = *reinterpret_cast<const float4*>(w + (size_t)c * F + tid * 4);

    float m = fmaxf(fmaxf(v.x, v.y), fmaxf(v.z, v.w));
#pragma unroll
    for (int o = 16; o; o >>= 1) m = fmaxf(m, __shfl_xor_sync(0xffffffffu, m, o));
    if ((tid & 31) == 0) red[tid >> 5] = m;
    __syncthreads();
    m = red[0];
#pragma unroll
    for (int i = 1; i < 8; i++) m = fmaxf(m, red[i]);
    __syncthreads();

    float e0 = __expf(v.x - m), e1 = __expf(v.y - m);
    float e2 = __expf(v.z - m), e3 = __expf(v.w - m);
    float s = (e0 + e1) + (e2 + e3);
#pragma unroll
    for (int o = 16; o; o >>= 1) s += __shfl_xor_sync(0xffffffffu, s, o);
    if ((tid & 31) == 0) red[tid >> 5] = s;
    __syncthreads();
    s = 0.0f;
#pragma unroll
    for (int i = 0; i < 8; i++) s += red[i];
    const float inv = 1.0f / s;

    // thread covers f = 4*tid..4*tid+3 == quad index q = tid
    ulonglong2 o4;
    o4.x = packf2(e0 * inv, e1 * inv);
    o4.y = packf2(e2 * inv, e3 * inv);
    g_ew4[(size_t)tid * C + c] = o4;
}

// ---------- Kernel B: 16 rows x 64 classes per block ----------
// 128 threads: cg = tid&31 (class pair), rg = (tid>>5)&1 (row group of 8), h = tid>>6 (f half)
__global__ __launch_bounds__(128, 3) void lse_kernel(const float* __restrict__ x,
                                                     float* __restrict__ out) {
    extern __shared__ float smem[];
    float* ex = smem;                         // TB*F floats (64 KB)
    float* mxs = smem + TB * F;               // TB floats
    unsigned long long* part =
        reinterpret_cast<unsigned long long*>(smem + TB * F + TB);  // TB*CH ull (8 KB)

    const int tid = threadIdx.x;
    const int lane = tid & 31;
    const int warp = tid >> 5;  // 0..3
    const int bt = blockIdx.x >> 1;
    const int ch = blockIdx.x & 1;
    const int b0 = bt * TB;

    // ---- phase 1: row max (each warp: 4 rows) ----
#pragma unroll
    for (int rr = 0; rr < 4; rr++) {
        const int r = warp * 4 + rr;
        const float4* xr = reinterpret_cast<const float4*>(x + (size_t)(b0 + r) * F);
        float m = -3.4e38f;
        for (int i = lane; i < F / 4; i += 32) {
            float4 v = xr[i];
            m = fmaxf(m, fmaxf(fmaxf(v.x, v.y), fmaxf(v.z, v.w)));
        }
#pragma unroll
        for (int o = 16; o; o >>= 1) m = fmaxf(m, __shfl_xor_sync(0xffffffffu, m, o));
        if (lane == 0) mxs[r] = m;
    }
    __syncthreads();

    // ---- phase 2: ex = exp(x - rowmax), vectorized ----
    const float4* xb = reinterpret_cast<const float4*>(x + (size_t)b0 * F);
    for (int i = tid; i < TB * F / 4; i += 128) {
        const int r = i >> 8;  // 256 float4 per row
        float4 v = xb[i];
        const float m = mxs[r];
        float4 e;
        e.x = __expf(v.x - m); e.y = __expf(v.y - m);
        e.z = __expf(v.z - m); e.w = __expf(v.w - m);
        *reinterpret_cast<float4*>(ex + i * 4) = e;
    }
    __syncthreads();

    // ---- phase 3: GEMM. thread: 2 classes x 8 rows x (F/2 features) ----
    const int cg = tid & 31;
    const int rg = (tid >> 5) & 1;
    const int h = tid >> 6;
    const int c0 = ch * CH + cg * 2;              // global class of acc0; acc1 = c0+1
    const ulonglong2* __restrict__ wq = g_ew4 + c0;
    const float* __restrict__ exb = ex + rg * 8 * F;

    unsigned long long acc0[8], acc1[8];
#pragma unroll
    for (int r = 0; r < 8; r++) { acc0[r] = 0ull; acc1[r] = 0ull; }

    const int qbeg = h * (F / 8);  // 128 quads per half

    // double-buffered weight quads, 4 q per group, 32 groups
    ulonglong2 wa[4], wb[4];
    int q = qbeg;
#pragma unroll
    for (int j = 0; j < 4; j++) {
        wa[j] = wq[(size_t)(q + j) * C];
        wb[j] = wq[(size_t)(q + j) * C + 1];
    }
#pragma unroll 1
    for (int g = 0; g < 32; g++) {
        int qn = q + 4;
        if (qn == qbeg + 128) qn = qbeg;  // dummy re-read on last iter (no OOB)
        ulonglong2 na[4], nb[4];
#pragma unroll
        for (int j = 0; j < 4; j++) {
            na[j] = wq[(size_t)(qn + j) * C];
            nb[j] = wq[(size_t)(qn + j) * C + 1];
        }
#pragma unroll
        for (int j = 0; j < 4; j++) {
            const float* ef = exb + (q + j) * 4;
#pragma unroll
            for (int r = 0; r < 8; r++) {
                ulonglong2 e = *reinterpret_cast<const ulonglong2*>(ef + r * F);
                fma2(acc0[r], e.x, wa[j].x);
                fma2(acc0[r], e.y, wa[j].y);
                fma2(acc1[r], e.x, wb[j].x);
                fma2(acc1[r], e.y, wb[j].y);
            }
        }
#pragma unroll
        for (int j = 0; j < 4; j++) { wa[j] = na[j]; wb[j] = nb[j]; }
        q = qn;
    }

    // ---- cross-half reduce + log ----
    if (h) {
#pragma unroll
        for (int r = 0; r < 8; r++) {
            ulonglong2 p; p.x = acc0[r]; p.y = acc1[r];
            *reinterpret_cast<ulonglong2*>(&part[(rg * 8 + r) * CH + cg * 2]) = p;
        }
    }
    __syncthreads();
    if (!h) {
#pragma unroll
        for (int r = 0; r < 8; r++) {
            const int row = rg * 8 + r;
            ulonglong2 p = *reinterpret_cast<const ulonglong2*>(&part[row * CH + cg * 2]);
            unsigned long long t0 = add2(acc0[r], p.x);
            unsigned long long t1 = add2(acc1[r], p.y);
            float a0, a1, b0f, b1f;
            unpack2(t0, a0, a1);
            unpack2(t1, b0f, b1f);
            float2 o;
            o.x = mxs[row] + logf(a0 + a1);
            o.y = mxs[row] + logf(b0f + b1f);
            *reinterpret_cast<float2*>(out + (size_t)(b0 + row) * C + c0) = o;
        }
    }
}

extern "C" void kernel_launch(void* const* d_in, const int* in_sizes, int n_in,
                              void* d_out, int out_size) {
    const float* x = (const float*)d_in[0];
    const float* w = (const float*)d_in[1];
    if (n_in >= 2 && in_sizes[0] == C * F && in_sizes[1] == B * F) {
        const float* t = x; x = w; w = t;
    }
    float* out = (float*)d_out;

    const int smem_bytes =
        (TB * F + TB) * (int)sizeof(float) + TB * CH * (int)sizeof(unsigned long long);
    cudaFuncSetAttribute(lse_kernel, cudaFuncAttributeMaxDynamicSharedMemorySize, smem_bytes);

    wprep_kernel<<<C, 256>>>(w);
    lse_kernel<<<(B / TB) * 2, 128, smem_bytes>>>(x, out);
}